// round 4
// baseline (speedup 1.0000x reference)
#include <cuda_runtime.h>
#include <math.h>

// Problem constants (fixed by setup_inputs)
#define BB 8
#define CC 256
#define HH 128
#define WW 128
#define NN (HH*WW)      // 16384
#define NN4 (NN/4)      // 4096
#define NB 16

#define TILE_N 64
#define NT4 16          // float4 per tile row (64 floats)
#define STRIDE4 17      // float4 stride per c-row (68 floats, conflict-free)
#define NTILES (NN/TILE_N)   // 256

// Output layout: reprVecs [16,8,256], sims [16,8,1,128,128], selpos [8,1,128,128]
#define OUT_REPR   0
#define OUT_SIMS   (NB*BB*CC)                  // 32768
#define OUT_SELPOS (OUT_SIMS + NB*BB*NN)       // 2129920

// Scratch (no allocations allowed -> __device__ globals)
__device__ float g_score[BB*NN];
__device__ float g_rv[BB*CC];
__device__ float g_repr[BB*CC];
__device__ float g_S[BB];
__device__ float g_pv[BB*NTILES];   // per-tile argmax value of NEW score
__device__ int   g_pi[BB*NTILES];   // per-tile argmax index

// ---------------------------------------------------------------------------
// Zero the selpos output region (d_out is poisoned before timing).
__global__ void init_kernel(float* __restrict__ out) {
    int i = blockIdx.x * blockDim.x + threadIdx.x;
    if (i < BB*NN) out[OUT_SELPOS + i] = 0.0f;
}

// ---------------------------------------------------------------------------
// Per-batch setup for iteration `iter` (one block per batch, 256 threads):
//   - normalize & emit repr for iteration iter-1 (if iter>0)
//   - if iter < NB: pick ind (reduce 256 per-tile argmax partials, or N/2 at
//     iter 0), bump selpos, gather rv, zero accumulators.
// Selection chain is atomic-free -> bit-deterministic across replays.
__global__ void setup_kernel(const float* __restrict__ x,
                             float* __restrict__ out, int iter) {
    const int b = blockIdx.x;
    const int t = threadIdx.x;   // 256 threads
    __shared__ float s_val[256];
    __shared__ int   s_idx[256];
    __shared__ int   s_ind;

    // 1) normalize previous iteration's representative vector
    if (iter > 0) {
        float S = g_S[b];
        out[OUT_REPR + (size_t)(iter-1)*BB*CC + b*CC + t] = g_repr[b*CC + t] / S;
    }
    if (iter >= NB) return;

    // 2) select index (first-max tie-break to match jnp.argmax)
    if (iter == 0) {
        if (t == 0) s_ind = NN / 2;
        __syncthreads();
    } else {
        s_val[t] = g_pv[b*NTILES + t];
        s_idx[t] = g_pi[b*NTILES + t];
        __syncthreads();
        for (int off = 128; off > 0; off >>= 1) {
            if (t < off) {
                float ov = s_val[t+off]; int oi = s_idx[t+off];
                if (ov > s_val[t] || (ov == s_val[t] && oi < s_idx[t])) {
                    s_val[t] = ov; s_idx[t] = oi;
                }
            }
            __syncthreads();
        }
        if (t == 0) s_ind = s_idx[0];
        __syncthreads();
    }
    const int ind = s_ind;

    // 3) selpos += 1 at selected position (single writer)
    if (t == 0) {
        out[OUT_SELPOS + b*NN + ind] += 1.0f;
        g_S[b] = 0.0f;
    }

    // 4) gather rv[b, c] = x[b, c, ind]; zero repr accumulator
    g_rv[b*CC + t]   = x[(size_t)b*CC*NN + (size_t)t*NN + ind];
    g_repr[b*CC + t] = 0.0f;
}

// ---------------------------------------------------------------------------
// Fused main pass for iteration `iter`:
// grid = (NTILES, BB), 256 threads. ONE float4 read of x per iteration (the
// traffic floor: both distance and weighted reduction consume the same tile).
//   phase 1: stream 64n x 256c tile -> smem (LDG.128/STS.128), per-n distance
//   phase 2: sim = exp(-sqrt(d2+eps)/20); emit sims; score update; tile argmax
//   phase 3: repr_raw[c] += sum_n tile[c][n]*sim[n]  (conflict-free LDS.128)
__global__ __launch_bounds__(256)
void main_kernel(const float4* __restrict__ x4, float* __restrict__ out,
                 int iter) {
    const int b  = blockIdx.y;
    const int tb = blockIdx.x;
    const int n0 = tb * TILE_N;
    const int t  = threadIdx.x;
    const int w  = t >> 5;          // warp 0..7
    const int l  = t & 31;
    const int n4 = l & 15;          // float4 index within row, 0..15
    const int c_off = l >> 4;       // 0..1

    extern __shared__ float sm[];
    float4* tile4 = (float4*)sm;                    // 256 * 17 float4
    float*  rv_s  = sm + CC*STRIDE4*4;              // 256
    float*  red   = rv_s + CC;                      // 8*16*4 = 512
    float*  sim_s = red + 512;                      // 64  (16B aligned)
    __shared__ float s_av[64];
    __shared__ int   s_ai[64];

    rv_s[t] = g_rv[b*CC + t];
    __syncthreads();

    // phase 1: warp w loads c = w*32 + step*2 + c_off, 16 float4 per row
    const float4* xb = x4 + (size_t)b*CC*NN4 + (n0 >> 2) + n4;
    float4 acc = make_float4(0.f, 0.f, 0.f, 0.f);
    #pragma unroll
    for (int step = 0; step < 16; step++) {
        const int c = w*32 + step*2 + c_off;
        float4 v = xb[(size_t)c * NN4];
        tile4[c*STRIDE4 + n4] = v;
        float r = rv_s[c];
        float dx = v.x - r, dy = v.y - r, dz = v.z - r, dw = v.w - r;
        acc.x = fmaf(dx, dx, acc.x);
        acc.y = fmaf(dy, dy, acc.y);
        acc.z = fmaf(dz, dz, acc.z);
        acc.w = fmaf(dw, dw, acc.w);
    }
    // fold c_off partner (lane l and l+16 share n4)
    acc.x += __shfl_down_sync(0xffffffffu, acc.x, 16);
    acc.y += __shfl_down_sync(0xffffffffu, acc.y, 16);
    acc.z += __shfl_down_sync(0xffffffffu, acc.z, 16);
    acc.w += __shfl_down_sync(0xffffffffu, acc.w, 16);
    if (c_off == 0) ((float4*)red)[w*16 + n4] = acc;
    __syncthreads();

    // phase 2: sim, sims output, score update, tile argmax partial
    if (t < TILE_N) {
        const int q = t >> 2, comp = t & 3;
        float d2 = 0.f;
        #pragma unroll
        for (int ww = 0; ww < 8; ww++) d2 += red[(ww*16 + q)*4 + comp];
        float sim = expf(-sqrtf(d2 + 1e-12f) * 0.05f);
        sim_s[t] = sim;
        out[OUT_SIMS + ((size_t)iter*BB + b)*NN + n0 + t] = sim;
        float* scp = g_score + (size_t)b*NN + n0 + t;
        float ns = 1.0f - sim;
        if (iter > 0) ns *= *scp;
        *scp = ns;
        s_av[t] = ns;
        s_ai[t] = n0 + t;
    }
    __syncthreads();

    // tile argmax of NEW score (used by next iteration's setup), 64 -> 1,
    // first-index tie-break
    #pragma unroll
    for (int off = 32; off > 0; off >>= 1) {
        if (t < off) {
            float ov = s_av[t+off]; int oi = s_ai[t+off];
            if (ov > s_av[t] || (ov == s_av[t] && oi < s_ai[t])) {
                s_av[t] = ov; s_ai[t] = oi;
            }
        }
        __syncthreads();
    }
    if (t == 0) {
        g_pv[b*NTILES + tb] = s_av[0];
        g_pi[b*NTILES + tb] = s_ai[0];
    }

    // block-partial S -> atomic (warp 0)
    if (t < 32) {
        float s2 = sim_s[t] + sim_s[t + 32];
        #pragma unroll
        for (int off = 16; off > 0; off >>= 1)
            s2 += __shfl_down_sync(0xffffffffu, s2, off);
        if (t == 0) atomicAdd(&g_S[b], s2);
    }

    // phase 3: repr_raw[c=t] += sum_n tile[c][n]*sim[n]; LDS.128 conflict-free
    // (stride 17 float4). 4 accumulator chains -> FFMA latency hidden.
    float r0 = 0.f, r1 = 0.f, r2 = 0.f, r3 = 0.f;
    const float4* trow = tile4 + t * STRIDE4;
    const float4* sv4  = (const float4*)sim_s;
    #pragma unroll
    for (int q = 0; q < NT4; q += 4) {
        float4 t0 = trow[q+0], s0 = sv4[q+0];
        float4 t1 = trow[q+1], s1 = sv4[q+1];
        float4 t2 = trow[q+2], s2 = sv4[q+2];
        float4 t3 = trow[q+3], s3 = sv4[q+3];
        r0 = fmaf(t0.x, s0.x, r0); r0 = fmaf(t0.y, s0.y, r0);
        r0 = fmaf(t0.z, s0.z, r0); r0 = fmaf(t0.w, s0.w, r0);
        r1 = fmaf(t1.x, s1.x, r1); r1 = fmaf(t1.y, s1.y, r1);
        r1 = fmaf(t1.z, s1.z, r1); r1 = fmaf(t1.w, s1.w, r1);
        r2 = fmaf(t2.x, s2.x, r2); r2 = fmaf(t2.y, s2.y, r2);
        r2 = fmaf(t2.z, s2.z, r2); r2 = fmaf(t2.w, s2.w, r2);
        r3 = fmaf(t3.x, s3.x, r3); r3 = fmaf(t3.y, s3.y, r3);
        r3 = fmaf(t3.z, s3.z, r3); r3 = fmaf(t3.w, s3.w, r3);
    }
    atomicAdd(&g_repr[b*CC + t], (r0 + r1) + (r2 + r3));
}

// ---------------------------------------------------------------------------
extern "C" void kernel_launch(void* const* d_in, const int* in_sizes, int n_in,
                              void* d_out, int out_size) {
    const float* x = (const float*)d_in[0];
    // d_in[1] (prior) is provably unused: at i==0 the reference overwrites the
    // score with 1-sim and forces ind = N/2. d_in[2] (nbVec) is the constant 16.
    float* out = (float*)d_out;

    const size_t smem = (CC*STRIDE4*4 + CC + 512 + 64) * sizeof(float); // 72960 B
    cudaFuncSetAttribute(main_kernel, cudaFuncAttributeMaxDynamicSharedMemorySize,
                         (int)smem);

    init_kernel<<<(BB*NN + 255) / 256, 256>>>(out);
    for (int i = 0; i < NB; i++) {
        setup_kernel<<<BB, 256>>>(x, out, i);
        main_kernel<<<dim3(NTILES, BB), 256, smem>>>((const float4*)x, out, i);
    }
    setup_kernel<<<BB, 256>>>(x, out, NB);   // final repr normalize only
}